// round 13
// baseline (speedup 1.0000x reference)
#include <cuda_runtime.h>
#include <math.h>
#include <float.h>

// Problem constants (fixed by the dataset)
#define S_   7
#define B_   2
#define C_   80
#define NGT  32
#define BT_  8192
#define CELLF 90                    // B*5 + C
#define NCELLS (BT_ * S_ * S_)      // 401408
#define NBOX   (NCELLS * B_)        // 802816
#define NGTS   (BT_ * NGT)          // 262144

#define NTHR 128
#define NBLK 1024                   // 131072 threads; 2 GTs per thread
#define NTOT (NBLK * NTHR)
#define GPT  (NGTS / NTOT)          // 2
#define NWARP (NTHR / 32)           // 4

// Per-block partial sums: [coord, obj, posconf_sq, cls, npos, noobj_all]
__device__ double g_part[NBLK][6];
__device__ unsigned int g_count = 0;

__device__ __forceinline__ float sigmoidf_(float x) {
    return 1.0f / (1.0f + __expf(-x));
}

// Cooperative softmax-sums for 32 GTs owned by one warp.
// Lane g's GT cell index is 'cellIdx'. On return, (ms,mq) on lane g hold
// (sum_exp, sum_exp^2) over the 80 class logits of lane g's cell.
__device__ __forceinline__ void coop_softmax_sums(
    const float* __restrict__ preds, int cellIdx, int lane,
    float& ms, float& mq)
{
    const unsigned FULL = 0xffffffffu;
    #pragma unroll 4
    for (int g = 0; g < 32; g++) {
        const int ci  = __shfl_sync(FULL, cellIdx, g);
        const int off = (ci & 1) << 1;                       // 0 (even) or 2 (odd)
        // 16B-aligned base. Odd cells shift back 2 floats; last cell is odd,
        // so lane<=22 accesses stay in-bounds for every cell (see masks).
        const float4* base = (const float4*)(preds + (size_t)ci * CELLF - off);

        float4 v = make_float4(0.f, 0.f, 0.f, 0.f);
        if (lane < 23) v = __ldg(base + lane);

        const int pos0 = 4 * lane - off;                     // cell-position of v.x
        const float e0 = ((unsigned)(pos0 + 0 - 10) < 80u) ? __expf(v.x) : 0.f;
        const float e1 = ((unsigned)(pos0 + 1 - 10) < 80u) ? __expf(v.y) : 0.f;
        const float e2 = ((unsigned)(pos0 + 2 - 10) < 80u) ? __expf(v.z) : 0.f;
        const float e3 = ((unsigned)(pos0 + 3 - 10) < 80u) ? __expf(v.w) : 0.f;

        float sl = (e0 + e1) + (e2 + e3);
        float ql = (e0*e0 + e1*e1) + (e2*e2 + e3*e3);
        #pragma unroll
        for (int o = 16; o; o >>= 1) {
            sl += __shfl_xor_sync(FULL, sl, o);
            ql += __shfl_xor_sync(FULL, ql, o);
        }
        if (lane == g) { ms = sl; mq = ql; }
    }
}

__global__ void __launch_bounds__(NTHR, 8)
yolo_loss_coopg(const float* __restrict__ preds,
                const float* __restrict__ gt_boxes,
                const int* __restrict__ gt_labels,
                const unsigned char* __restrict__ gt_valid,
                float* __restrict__ out)
{
    const int tid  = threadIdx.x;
    const int lane = tid & 31;
    const int wid  = tid >> 5;
    const int t0   = blockIdx.x * NTHR + tid;
    const unsigned FULL = 0xffffffffu;

    float coord = 0.f, obj = 0.f, posconf = 0.f, clsl = 0.f, npos = 0.f, noobj = 0.f;

    // ===== Phase 2 conf loads hoisted: independent MLP =====
    {
        const float a0 = __ldg(preds + (size_t)t0 * CELLF + 4);
        const float b0 = __ldg(preds + (size_t)t0 * CELLF + 9);
        const float a1 = __ldg(preds + (size_t)(t0 + NTOT) * CELLF + 4);
        const float b1 = __ldg(preds + (size_t)(t0 + NTOT) * CELLF + 9);
        const float a2 = __ldg(preds + (size_t)(t0 + 2 * NTOT) * CELLF + 4);
        const float b2 = __ldg(preds + (size_t)(t0 + 2 * NTOT) * CELLF + 9);
        float a3 = 0.f, b3 = 0.f;
        const bool has4 = (t0 + 3 * NTOT) < NCELLS;
        if (has4) {
            a3 = __ldg(preds + (size_t)(t0 + 3 * NTOT) * CELLF + 4);
            b3 = __ldg(preds + (size_t)(t0 + 3 * NTOT) * CELLF + 9);
        }
        const float s0 = sigmoidf_(a0), s1 = sigmoidf_(b0);
        const float s2 = sigmoidf_(a1), s3 = sigmoidf_(b1);
        const float s4 = sigmoidf_(a2), s5 = sigmoidf_(b2);
        noobj = s0*s0 + s1*s1 + s2*s2 + s3*s3 + s4*s4 + s5*s5;
        if (has4) {
            const float s6 = sigmoidf_(a3), s7 = sigmoidf_(b3);
            noobj += s6*s6 + s7*s7;
        }
    }

    // ===== GT metadata + cell indices for both GTs =====
    int   cellIdxA[GPT];
    float4 gbA[GPT];
    int   labelA[GPT];
    float mvalA[GPT];
    #pragma unroll
    for (int g = 0; g < GPT; g++) {
        const int t = t0 + g * NTOT;
        mvalA[g]  = (__ldg(gt_valid + t) != 0) ? 1.0f : 0.0f;
        gbA[g]    = __ldg((const float4*)gt_boxes + t);
        labelA[g] = __ldg(gt_labels + t);
        const float cx = (gbA[g].x + gbA[g].z) * 0.5f;
        const float cy = (gbA[g].y + gbA[g].w) * 0.5f;
        const int gi = min(max((int)floorf(cx * (float)S_), 0), S_ - 1);
        const int gj = min(max((int)floorf(cy * (float)S_), 0), S_ - 1);
        cellIdxA[g] = (t >> 5) * (S_ * S_) + gj * S_ + gi;
    }

    // ===== Cooperative coalesced softmax sums (one warp-load per cell) =====
    float ms[GPT], mq[GPT];
    #pragma unroll
    for (int g = 0; g < GPT; g++)
        coop_softmax_sums(preds, cellIdxA[g], lane, ms[g], mq[g]);

    // ===== Tail: thread-per-GT (box/IoU/coord + cls term) =====
    #pragma unroll
    for (int g = 0; g < GPT; g++) {
        const float4 gb = gbA[g];
        const int label = labelA[g];
        const float mval = mvalA[g];
        const int cellIdx = cellIdxA[g];

        const float x1 = gb.x, y1 = gb.y, x2 = gb.z, y2 = gb.w;
        const float cx = (x1 + x2) * 0.5f;
        const float cy = (y1 + y2) * 0.5f;
        const float w  = fmaxf(x2 - x1, 1e-6f);
        const float h  = fmaxf(y2 - y1, 1e-6f);
        const int gi = min(max((int)floorf(cx * (float)S_), 0), S_ - 1);
        const int gj = min(max((int)floorf(cy * (float)S_), 0), S_ - 1);

        const float* cell = preds + (size_t)cellIdx * CELLF;

        // label logit (line is L1/L2-hot from the coop pass)
        const float cl = __ldg(cell + 10 + label);

        // box floats 0..9 via the aligned-vec4 trick (L1/L2 hits)
        const int off = (cellIdx & 1) << 1;
        const float4* v4 = (const float4*)(cell - off);
        float p[12];
        {
            const float4 a  = __ldg(v4 + 0);
            const float4 bq = __ldg(v4 + 1);
            const float4 c  = __ldg(v4 + 2);
            p[0]=a.x;  p[1]=a.y;  p[2]=a.z;  p[3]=a.w;
            p[4]=bq.x; p[5]=bq.y; p[6]=bq.z; p[7]=bq.w;
            p[8]=c.x;  p[9]=c.y;  p[10]=c.z; p[11]=c.w;
        }
        float bx[10];
        #pragma unroll
        for (int j = 0; j < 10; j++) bx[j] = (off != 0) ? p[j + 2] : p[j];

        const float el  = __expf(cl);
        const float inv = 1.0f / ms[g];
        const float cls_term = mq[g] * inv * inv - 2.0f * el * inv + 1.0f;

        const float area_g = (x2 - x1) * (y2 - y1);
        float iou[2], sxk[2], syk[2], twk[2], thk[2], tok[2];
        #pragma unroll
        for (int k = 0; k < 2; k++) {
            const float tx = bx[k*5+0], ty = bx[k*5+1];
            const float tw = bx[k*5+2], th = bx[k*5+3];
            const float sx = sigmoidf_(tx);
            const float sy = sigmoidf_(ty);
            const float pw = tw * tw, ph = th * th;
            const float px = (sx + (float)gi) * (1.0f / S_);
            const float py = (sy + (float)gj) * (1.0f / S_);
            const float px1 = px - 0.5f * pw, px2v = px + 0.5f * pw;
            const float py1 = py - 0.5f * ph, py2v = py + 0.5f * ph;
            const float iw = fmaxf(0.f, fminf(px2v, x2) - fmaxf(px1, x1));
            const float ih = fmaxf(0.f, fminf(py2v, y2) - fmaxf(py1, y1));
            const float inter = iw * ih;
            iou[k] = inter / (pw * ph + area_g - inter + 1e-6f);
            sxk[k] = sx; syk[k] = sy; twk[k] = tw; thk[k] = th; tok[k] = bx[k*5+4];
        }
        const int   best = (iou[1] > iou[0]) ? 1 : 0;
        const float iou_best = fmaxf(iou[0], iou[1]);

        const float so  = sigmoidf_(tok[best]);
        const float tgx = cx * (float)S_ - (float)gi;
        const float tgy = cy * (float)S_ - (float)gj;
        const float tgw = sqrtf(w), tgh = sqrtf(h);
        const float dx = sxk[best] - tgx, dy = syk[best] - tgy;
        const float dw = twk[best] - tgw, dh = thk[best] - tgh;
        const float dob = so - iou_best;

        coord   += mval * (dx*dx + dy*dy + dw*dw + dh*dh);
        obj     += mval * dob * dob;
        posconf += mval * so * so;
        npos    += mval;
        clsl    += mval * cls_term;
    }

    // ================= Block reduction -> g_part =================
    float vals[6] = {coord, obj, posconf, clsl, npos, noobj};
    #pragma unroll
    for (int j = 0; j < 6; j++) {
        #pragma unroll
        for (int o = 16; o; o >>= 1)
            vals[j] += __shfl_xor_sync(FULL, vals[j], o);
    }
    __shared__ double sh[NWARP][6];
    if (lane == 0) {
        #pragma unroll
        for (int j = 0; j < 6; j++) sh[wid][j] = (double)vals[j];
    }
    __syncthreads();
    if (tid < 6) {
        double acc = 0.0;
        #pragma unroll
        for (int wI = 0; wI < NWARP; wI++) acc += sh[wI][tid];
        g_part[blockIdx.x][tid] = acc;
    }

    // ================= Grid-wide finalize: last block reduces =================
    __shared__ bool is_last;
    __threadfence();
    if (tid == 0) {
        const unsigned prev = atomicAdd(&g_count, 1u);
        is_last = (prev == (unsigned)(NBLK - 1));
        if (is_last) g_count = 0u;          // reset for next graph replay
    }
    __syncthreads();
    if (!is_last) return;

    double a[6] = {0, 0, 0, 0, 0, 0};
    for (int bb = tid; bb < NBLK; bb += NTHR) {
        #pragma unroll
        for (int j = 0; j < 6; j++) a[j] += __ldcg(&g_part[bb][j]);
    }
    #pragma unroll
    for (int j = 0; j < 6; j++) {
        #pragma unroll
        for (int o = 16; o; o >>= 1)
            a[j] += __shfl_xor_sync(FULL, a[j], o);
    }
    __shared__ double shf[NWARP][6];
    if (lane == 0) {
        #pragma unroll
        for (int j = 0; j < 6; j++) shf[wid][j] = a[j];
    }
    __syncthreads();
    if (tid == 0) {
        double tt[6];
        #pragma unroll
        for (int j = 0; j < 6; j++) {
            tt[j] = 0.0;
            for (int wI = 0; wI < NWARP; wI++) tt[j] += shf[wI][j];
        }
        const double nposd = fmax(tt[4], 1.0);
        const double nneg  = fmax((double)NBOX - tt[4], 1.0);
        const double ncell = fmax(tt[4], 1.0);   // GT cells are distinct per batch item
        const double loss = 5.0 * tt[0] / nposd          // LC * coord
                          + tt[1] / nposd                // obj
                          + 0.5 * (tt[5] - tt[2]) / nneg // LN * noobj (all - positive)
                          + tt[3] / ncell;               // cls
        *out = (float)loss;
    }
}

extern "C" void kernel_launch(void* const* d_in, const int* in_sizes, int n_in,
                              void* d_out, int out_size)
{
    const float*         preds     = (const float*)d_in[0];
    const float*         gt_boxes  = (const float*)d_in[1];
    const int*           gt_labels = (const int*)d_in[2];
    const unsigned char* gt_valid  = (const unsigned char*)d_in[3];
    float* out = (float*)d_out;

    yolo_loss_coopg<<<NBLK, NTHR>>>(preds, gt_boxes, gt_labels, gt_valid, out);
}